// round 16
// baseline (speedup 1.0000x reference)
#include <cuda_runtime.h>
#include <cuda_bf16.h>
#include <cstdint>
#include <math.h>

typedef unsigned long long u64;

#define L_   256
#define B_   128
#define D_   256
#define H_   256
#define NCOL 2048            // 2 dirs * 4H packed gate columns
#define HALF 16777216        // L*B*2H  (cells block size; hiddens follow)

// rec smem layout (float offsets)
#define F_W      0           // W64: [128 kp][64 cpair][2 j] u64 k-pairs = 131072 B
#define F_H      32768       // h:  [2 wg][32 row][256] plain fp32        = 65536 B
#define F_G      49152       // gates: [2 wg][32][132] fp32               = 33792 B
#define F_OFF    57600       // round offsets: 258 int
#define F_LP     57858       // chunk worklist: [2 wg][32] int
#define F_PAR2   57922       // chunk parents:  [2 wg][32] int
#define DYN_SMEM 231944

// ------------------------- __device__ scratch (no runtime alloc) -------------------------
__device__ float g_wx[(size_t)NCOL * D_];
__device__ float g_bias[NCOL];
__device__ float g_xi[(size_t)L_ * B_ * NCOL];
__device__ float g_acc_c[(size_t)B_ * 257 * H_];
__device__ float g_acc_h[(size_t)B_ * 257 * H_];
__device__ float g_td_h[(size_t)L_ * B_ * H_];
__device__ float g_td_c[(size_t)L_ * B_ * H_];
__device__ int   g_rankbuf[2 * 128 * 256];
__device__ int   g_wl[16 * 4096];
__device__ int   g_offs[16 * 258];
__device__ int   g_nrounds[16];

// ------------------------- helpers -------------------------
__device__ __forceinline__ void fma2(u64& c, u64 a, u64 b) {
    asm("fma.rn.f32x2 %0, %1, %2, %3;" : "=l"(c) : "l"(a), "l"(b), "l"(c));
}
__device__ __forceinline__ float2 up2(u64 v) {
    float2 f; asm("mov.b64 {%0, %1}, %2;" : "=f"(f.x), "=f"(f.y) : "l"(v)); return f;
}
__device__ __forceinline__ float sigm(float x) { return 1.0f / (1.0f + __expf(-x)); }
__device__ __forceinline__ void wgbar(int wg) {
    asm volatile("bar.sync %0, 256;" :: "r"(wg + 1) : "memory");
}

// ------------------------- rank kernel -------------------------
__global__ void rank_kernel(const int* __restrict__ parents) {
    int tid = threadIdx.x;
    int dir = tid >> 7, b = tid & 127;
    int rr[256];
    if (dir) {
        rr[0] = 0;
        for (int i = 1; i < 256; i++) rr[i] = rr[parents[i * B_ + b]] + 1;
    } else {
        for (int i = 0; i < 256; i++) rr[i] = 0;
        for (int i = 255; i >= 1; i--) {
            int p = parents[i * B_ + b];
            int v = rr[i] + 1;
            if (rr[p] < v) rr[p] = v;
        }
    }
    for (int i = 0; i < 256; i++) g_rankbuf[(dir * 128 + b) * 256 + i] = rr[i];
}

// ------------------------- worklist kernel -------------------------
__global__ void wlist_kernel() {
    __shared__ int cnt[258], pos[258];
    __shared__ int maxr;
    int cl = blockIdx.x;
    int dir = cl >> 3, bg = cl & 7;
    int t = threadIdx.x;
    for (int i = t; i < 258; i += 256) cnt[i] = 0;
    if (t == 0) maxr = 0;
    __syncthreads();
    for (int idx = t; idx < 4096; idx += 256) {
        int bl = idx >> 8, n = idx & 255;
        int rk = g_rankbuf[(dir * 128 + bg * 16 + bl) * 256 + n];
        atomicAdd(&cnt[rk], 1);
        atomicMax(&maxr, rk);
    }
    __syncthreads();
    if (t == 0) {
        int acc = 0;
        for (int i = 0; i <= maxr + 1; i++) {
            pos[i] = acc;
            g_offs[cl * 258 + i] = acc;
            acc += cnt[i];
        }
        g_nrounds[cl] = maxr + 1;
    }
    __syncthreads();
    for (int idx = t; idx < 4096; idx += 256) {
        int bl = idx >> 8, n = idx & 255;
        int rk = g_rankbuf[(dir * 128 + bg * 16 + bl) * 256 + n];
        int p = atomicAdd(&pos[rk], 1);
        g_wl[cl * 4096 + p] = (bl << 8) | n;
    }
}

// ------------------------- pack x-weights + fused biases -------------------------
__global__ void pack_wx_kernel(const float* __restrict__ ioux_w, const float* __restrict__ ioux_b,
                               const float* __restrict__ iouh_b, const float* __restrict__ fx_w,
                               const float* __restrict__ fx_b, const float* __restrict__ fh_b,
                               int base) {
    int c = blockIdx.x;
    int k = threadIdx.x;
    const float* src = (c < 768) ? (ioux_w + (size_t)c * D_) : (fx_w + (size_t)(c - 768) * D_);
    g_wx[(size_t)(base + c) * D_ + k] = src[k];
    if (k == 0)
        g_bias[base + c] = (c < 768) ? (ioux_b[c] + iouh_b[c]) : (fx_b[c - 768] + fh_b[c - 768]);
}

// ------------------------- precompute GEMM: broadcast-A, k-lane f32x2 -------------------------
// 64x64 tile, 256 threads = 8 warps; warp w owns rows w*8..w*8+7 x all 64 cols;
// lane owns cols (2*lane, 2*lane+1). A plain fp32 (broadcast reads), W k-pair u64s.
__global__ __launch_bounds__(256) void xgemm_kernel(const float* __restrict__ A) {
    __shared__ float As[64 * 36];      // [row][k] stride 36
    __shared__ u64 Bs[16 * 64];        // [kp][cpair*2+j]
    float* Bsf = (float*)Bs;
    int mBase = blockIdx.x * 64;
    int nBase = blockIdx.y * 64;
    int t = threadIdx.x;
    int lane = t & 31;
    int w = t >> 5;
    int lm = t >> 2, lk = (t & 3) * 8;     // A stage: 4 thr per row
    int cn = t & 63, kr = (t >> 6) * 8;    // B stage: 4 thr per col

    u64 acc[16];
#pragma unroll
    for (int i = 0; i < 16; i++) acc[i] = 0ull;

    for (int kt = 0; kt < 256; kt += 32) {
        __syncthreads();
        // stage A tile [64 x 32] plain fp32
        {
            const float* ap = A + (size_t)(mBase + lm) * D_ + kt + lk;
            float4 a0 = *(const float4*)(ap);
            float4 a1 = *(const float4*)(ap + 4);
            *(float4*)(As + lm * 36 + lk) = a0;
            *(float4*)(As + lm * 36 + lk + 4) = a1;
        }
        // stage B tile [64 cols x 32 k] into k-pair u64 layout
        {
            const float* wp = g_wx + (size_t)(nBase + cn) * D_ + kt + kr;
            float4 b0 = *(const float4*)(wp);
            float4 b1 = *(const float4*)(wp + 4);
            float v[8] = {b0.x, b0.y, b0.z, b0.w, b1.x, b1.y, b1.z, b1.w};
#pragma unroll
            for (int k = 0; k < 8; k++) {
                int kk = kr + k;
                Bsf[((kk >> 1) * 64 + (cn >> 1) * 2 + (cn & 1)) * 2 + (kk & 1)] = v[k];
            }
        }
        __syncthreads();
        // GEMM over this k-tile: 8 kq iterations of 4k
        const float* hb = As + (w * 8) * 36;
        const u64* wb = Bs + lane * 2;
#pragma unroll
        for (int kq = 0; kq < 8; kq++) {
            ulonglong2 wv0 = *(const ulonglong2*)(wb + (2 * kq) * 64);
            ulonglong2 wv1 = *(const ulonglong2*)(wb + (2 * kq + 1) * 64);
#pragma unroll
            for (int rr = 0; rr < 8; rr++) {
                ulonglong2 hv = *(const ulonglong2*)(hb + rr * 36 + kq * 4);
                fma2(acc[rr * 2 + 0], hv.x, wv0.x);
                fma2(acc[rr * 2 + 1], hv.x, wv0.y);
                fma2(acc[rr * 2 + 0], hv.y, wv1.x);
                fma2(acc[rr * 2 + 1], hv.y, wv1.y);
            }
        }
    }
    // epilogue: horizontal add + bias, store
    float2 bias2 = *(const float2*)(g_bias + nBase + lane * 2);
#pragma unroll
    for (int rr = 0; rr < 8; rr++) {
        float2 e0 = up2(acc[rr * 2 + 0]);
        float2 e1 = up2(acc[rr * 2 + 1]);
        float2 o = make_float2(e0.x + e0.y + bias2.x, e1.x + e1.y + bias2.y);
        *(float2*)(g_xi + (size_t)(mBase + w * 8 + rr) * NCOL + nBase + lane * 2) = o;
    }
}

// ------------------------- recurrent kernel: broadcast-h 8x2 tiles, 2 wg x 32-row chunks ----
// 128 CTAs = 16 clusters of 8. cluster = (dir, batch group of 16); rank r owns 32 h-dims
// (128 gate cols). W in smem as k-pair u64s: idx = kp*128 + cp*2 + j -> W[col=2cp+j][2kp..2kp+1].
// Warp = 8 rows x 64 cols (broadcast h, 1 wf/load); lane = 8 rows x 2 cols (16 u64 acc).
// Crossbar = fma floor. Gather: one row per warp-instr, contiguous lanes (conflict-free).
__global__ __launch_bounds__(512, 1) __cluster_dims__(8, 1, 1)
void rec_kernel(const int* __restrict__ parents,
                const float* __restrict__ dt_iouh_w, const float* __restrict__ dt_fh_w,
                const float* __restrict__ td_iouh_w, const float* __restrict__ td_fh_w,
                float* __restrict__ out) {
    extern __shared__ float smem[];
    float* Wf      = smem + F_W;
    u64*   W64     = (u64*)(smem + F_W);
    float* h_s     = smem + F_H;               // [2][32][256]
    float* gates_s = smem + F_G;               // [2][32][132]
    int*   off_s   = (int*)(smem + F_OFF);
    int*   lp_s    = (int*)(smem + F_LP);      // [2][32]
    int*   pp_s    = (int*)(smem + F_PAR2);    // [2][32]

    const int blk = blockIdx.x;
    const int r   = blk & 7;
    const int cid = blk >> 3;
    const int dir = cid >> 3;
    const int bg  = cid & 7;
    const int t   = threadIdx.x;
    const int lane = t & 31;
    const int wg   = t >> 8;           // warpgroup 0..1
    const int t256 = t & 255;
    const int w8   = t256 >> 5;        // warp within warpgroup 0..7

    const float* iouh = dir ? td_iouh_w : dt_iouh_w;
    const float* fh   = dir ? td_fh_w : dt_fh_w;

    // ---- one-time: Wh slice -> k-pair/col-pair u64 layout ----
    {
        int cc = t & 127;              // gate column 0..127 (g*32+j)
        int g = cc >> 5, j = cc & 31;
        const float* src = (g < 3) ? (iouh + (size_t)(g * 256 + r * 32 + j) * H_)
                                   : (fh + (size_t)(r * 32 + j) * H_);
        int k0 = (t >> 7) * 64;
        for (int k = k0; k < k0 + 64; k++) {
            int u64idx = (k >> 1) * 128 + (cc >> 1) * 2 + (cc & 1);
            Wf[u64idx * 2 + (k & 1)] = src[k];
        }
    }
    for (int i = t; i < 258; i += 512) off_s[i] = g_offs[cid * 258 + i];
    const int nR = g_nrounds[cid];
    __syncthreads();

    // GEMM mapping: warp w8 -> rows (w8&3)*8..+7, col half (w8>>2)*64; lane -> 2 cols
    const int rowg  = (w8 & 3) * 8;
    const int chalf = w8 >> 2;
    const int cp    = chalf * 32 + lane;   // global col pair 0..63
    // epilogue mapping: erow (32 rows), ejj = 4 h-dims
    const int erow = t256 >> 3;
    const int ejj  = (t256 & 7) * 4;

    float* myh   = h_s + wg * 8192;
    float* myg   = gates_s + wg * 32 * 132;
    int*   mylp  = lp_s + wg * 32;
    int*   mypp  = pp_s + wg * 32;

    for (int rd = 0; rd < nR; rd++) {
        const int base = off_s[rd];
        const int end  = off_s[rd + 1];
        const int C32 = (end - base + 31) >> 5;

        for (int ci = wg; ci < C32; ci += 2) {
            // ---- stage: 32-row chunk worklist + parents ----
            if (t256 < 32) {
                int ridx = base + ci * 32 + t256;
                int pair = (ridx < end) ? __ldg(&g_wl[cid * 4096 + ridx]) : -1;
                mylp[t256] = pair;
                mypp[t256] = (pair >= 0)
                    ? __ldg(&parents[(pair & 255) * B_ + bg * 16 + (pair >> 8)]) : 0;
            }
            wgbar(wg);   // #0: lp/pp visible

            // ---- gather h: warp w8 -> rows w8*4..+3, lanes contiguous (conflict-free) ----
#pragma unroll
            for (int q = 0; q < 4; q++) {
                int row = w8 * 4 + q;
                int pair = mylp[row];
                float4 z = make_float4(0.f, 0.f, 0.f, 0.f);
                const float* hsrc = nullptr;
                bool zero = true;
                if (pair >= 0) {
                    int bl = pair >> 8, n = pair & 255;
                    int b = bg * 16 + bl;
                    int p = mypp[row];
                    if (dir) {
                        if (p != 256) { hsrc = g_td_h + ((size_t)p * B_ + b) * 256; zero = false; }
                    } else {
                        hsrc = g_acc_h + ((size_t)b * 257 + n) * 256; zero = false;
                    }
                }
                float4 v0 = zero ? z : __ldcg((const float4*)(hsrc + lane * 4));
                float4 v1 = zero ? z : __ldcg((const float4*)(hsrc + 128 + lane * 4));
                *(float4*)(myh + row * 256 + lane * 4) = v0;
                *(float4*)(myh + row * 256 + 128 + lane * 4) = v1;
            }
            // epilogue operands into regs
            float4 exi0, exi1, exi2, exi3, esc;
            exi0 = exi1 = exi2 = exi3 = esc = make_float4(0.f, 0.f, 0.f, 0.f);
            {
                int pair = mylp[erow];
                if (pair >= 0) {
                    int bl = pair >> 8, n = pair & 255;
                    int b = bg * 16 + bl;
                    int p = mypp[erow];
                    const float* xb = g_xi + ((size_t)n * B_ + b) * NCOL + dir * 1024 + r * 32 + ejj;
                    exi0 = __ldcg((const float4*)(xb));
                    exi1 = __ldcg((const float4*)(xb + 256));
                    exi2 = __ldcg((const float4*)(xb + 512));
                    exi3 = __ldcg((const float4*)(xb + 768));
                    if (dir) {
                        if (p != 256)
                            esc = __ldcg((const float4*)(g_td_c + ((size_t)p * B_ + b) * 256 + r * 32 + ejj));
                    } else {
                        esc = __ldcg((const float4*)(g_acc_c + ((size_t)b * 257 + n) * 256 + r * 32 + ejj));
                    }
                }
            }
            wgbar(wg);   // #1: h staged

            // ---- GEMM: 8 rows x 2 cols per lane, f32x2 on K, broadcast h ----
            {
                u64 acc[16];
#pragma unroll
                for (int i = 0; i < 16; i++) acc[i] = 0ull;
                const float* hb = myh + rowg * 256;
                const u64* wb = W64 + cp * 2;
#pragma unroll 4
                for (int kq = 0; kq < 64; kq++) {
                    ulonglong2 wv0 = *(const ulonglong2*)(wb + (2 * kq) * 128);
                    ulonglong2 wv1 = *(const ulonglong2*)(wb + (2 * kq + 1) * 128);
#pragma unroll
                    for (int rr = 0; rr < 8; rr++) {
                        ulonglong2 hv = *(const ulonglong2*)(hb + rr * 256 + kq * 4);
                        fma2(acc[rr * 2 + 0], hv.x, wv0.x);
                        fma2(acc[rr * 2 + 1], hv.x, wv0.y);
                        fma2(acc[rr * 2 + 0], hv.y, wv1.x);
                        fma2(acc[rr * 2 + 1], hv.y, wv1.y);
                    }
                }
                int gc = cp * 2;
#pragma unroll
                for (int rr = 0; rr < 8; rr++) {
                    float2 e0 = up2(acc[rr * 2 + 0]);
                    float2 e1 = up2(acc[rr * 2 + 1]);
                    *(float2*)(myg + (rowg + rr) * 132 + gc) =
                        make_float2(e0.x + e0.y, e1.x + e1.y);
                }
            }
            wgbar(wg);   // #2: gates ready

            // ---- epilogue: +xi, nonlinearities, state update, scatter (4 dims/thread) ----
            {
                int pair = mylp[erow];
                if (pair >= 0) {
                    int bl = pair >> 8, n = pair & 255;
                    int b = bg * 16 + bl;
                    int p = mypp[erow];
                    float4 gi = *(const float4*)(myg + erow * 132 + ejj);
                    float4 go = *(const float4*)(myg + erow * 132 + 32 + ejj);
                    float4 gu = *(const float4*)(myg + erow * 132 + 64 + ejj);
                    float4 gf = *(const float4*)(myg + erow * 132 + 96 + ejj);
                    float ii[4] = {gi.x + exi0.x, gi.y + exi0.y, gi.z + exi0.z, gi.w + exi0.w};
                    float oo[4] = {go.x + exi1.x, go.y + exi1.y, go.z + exi1.z, go.w + exi1.w};
                    float uu[4] = {gu.x + exi2.x, gu.y + exi2.y, gu.z + exi2.z, gu.w + exi2.w};
                    float ff[4] = {gf.x + exi3.x, gf.y + exi3.y, gf.z + exi3.z, gf.w + exi3.w};
                    float scv[4] = {esc.x, esc.y, esc.z, esc.w};
                    float cv[4], hv[4];
#pragma unroll
                    for (int d = 0; d < 4; d++) {
                        float ig = sigm(ii[d]);
                        float og = sigm(oo[d]);
                        float ug = tanhf(uu[d]);
                        float fg = sigm(ff[d]);
                        cv[d] = ig * ug + fg * scv[d];
                        hv[d] = og * tanhf(cv[d]);
                    }
                    float4 cf = make_float4(cv[0], cv[1], cv[2], cv[3]);
                    float4 hf = make_float4(hv[0], hv[1], hv[2], hv[3]);
                    size_t orow = ((size_t)n * B_ + b) * 512 + (size_t)dir * 256 + r * 32 + ejj;
                    __stcg((float4*)(out + orow), cf);
                    __stcg((float4*)(out + HALF + orow), hf);
                    if (dir) {
                        size_t trow = ((size_t)n * B_ + b) * 256 + r * 32 + ejj;
                        __stcg((float4*)(g_td_h + trow), hf);
                        __stcg((float4*)(g_td_c + trow), cf);
                    } else {
                        size_t arow = ((size_t)b * 257 + p) * 256 + r * 32 + ejj;
#pragma unroll
                        for (int d = 0; d < 4; d++) {
                            atomicAdd(&g_acc_h[arow + d], hv[d]);
                            atomicAdd(&g_acc_c[arow + d], cv[d]);
                        }
                    }
                }
            }
            wgbar(wg);   // #3: chunk complete
        }

        // ---- all warpgroups done: publish round's writes to peer ranks ----
        __syncthreads();
        asm volatile("barrier.cluster.arrive.aligned;" ::: "memory");
        asm volatile("barrier.cluster.wait.aligned;" ::: "memory");
    }
}

// ------------------------- launch -------------------------
extern "C" void kernel_launch(void* const* d_in, const int* in_sizes, int n_in,
                              void* d_out, int out_size) {
    const float* inputs = (const float*)d_in[0];
    const int* parents = (const int*)d_in[2];

    rank_kernel<<<1, 256>>>(parents);
    wlist_kernel<<<16, 256>>>();

    pack_wx_kernel<<<1024, 256>>>((const float*)d_in[3], (const float*)d_in[4],
                                  (const float*)d_in[6], (const float*)d_in[7],
                                  (const float*)d_in[8], (const float*)d_in[10], 0);
    pack_wx_kernel<<<1024, 256>>>((const float*)d_in[11], (const float*)d_in[12],
                                  (const float*)d_in[14], (const float*)d_in[15],
                                  (const float*)d_in[16], (const float*)d_in[18], 1024);

    dim3 gg(512, 32);
    xgemm_kernel<<<gg, 256>>>(inputs);

    void* accc = nullptr; void* acch = nullptr;
    cudaGetSymbolAddress(&accc, g_acc_c);
    cudaGetSymbolAddress(&acch, g_acc_h);
    cudaMemsetAsync(accc, 0, sizeof(float) * (size_t)B_ * 257 * H_);
    cudaMemsetAsync(acch, 0, sizeof(float) * (size_t)B_ * 257 * H_);

    cudaFuncSetAttribute(rec_kernel, cudaFuncAttributeMaxDynamicSharedMemorySize, DYN_SMEM);
    rec_kernel<<<128, 512, DYN_SMEM>>>(parents,
                                       (const float*)d_in[5], (const float*)d_in[9],
                                       (const float*)d_in[13], (const float*)d_in[17],
                                       (float*)d_out);
}